// round 1
// baseline (speedup 1.0000x reference)
#include <cuda_runtime.h>

// Problem dims
#define Bv 32
#define Cv 1024
#define Nv 784
#define Mv 4
#define N4v 196      // Nv/4
#define NCH 8
#define PCH 128      // Cv/NCH

// Scratch (device globals — no allocation allowed)
__device__ float  g_invnorm[Bv][Cv];
__device__ float4 g_wsc[Bv][Cv];                 // (Wm[m,p]*invnorm[b,p]) packed over m
__device__ float4 g_tpart[Bv][NCH][Mv][N4v];     // partial t over p-chunks
__device__ float4 g_h[Bv][N4v];                  // h[b,n] = sum_m g/s

// ---------------------------------------------------------------------------
// Kernel A: per-(b,p) L2 norm over the 784 pixels; also precompute Wscaled.
// Grid (32, 128), 256 threads = 8 warps, warp w handles p = blockIdx.y*8+w.
// ---------------------------------------------------------------------------
__global__ void __launch_bounds__(256) kA(const float* __restrict__ x,
                                          const float* __restrict__ Wm) {
    int b = blockIdx.x;
    int warp = threadIdx.x >> 5, lane = threadIdx.x & 31;
    int p = (blockIdx.y << 3) + warp;
    const float4* row = reinterpret_cast<const float4*>(x) + ((size_t)b * Cv + p) * N4v;
    float s = 0.f;
#pragma unroll
    for (int k = 0; k < 7; ++k) {
        int idx = lane + k * 32;
        if (idx < N4v) {
            float4 v = row[idx];
            s += v.x * v.x + v.y * v.y + v.z * v.z + v.w * v.w;
        }
    }
#pragma unroll
    for (int o = 16; o; o >>= 1) s += __shfl_xor_sync(0xffffffffu, s, o);
    if (lane == 0) {
        float inv = 1.0f / fmaxf(sqrtf(s), 1e-10f);
        g_invnorm[b][p] = inv;
        float4 w;
        w.x = Wm[0 * Cv + p] * inv;
        w.y = Wm[1 * Cv + p] * inv;
        w.z = Wm[2 * Cv + p] * inv;
        w.w = Wm[3 * Cv + p] * inv;
        g_wsc[b][p] = w;
    }
}

// ---------------------------------------------------------------------------
// Kernel B: t[b,m,n] partials. Grid (32, 8), 196 threads; thread t owns
// pixel quad n=4t..4t+3, loops over its 128-channel chunk. No atomics.
// ---------------------------------------------------------------------------
__global__ void __launch_bounds__(196) kB(const float* __restrict__ x) {
    int b = blockIdx.x, cc = blockIdx.y;
    int t = threadIdx.x;
    const float4* xb = reinterpret_cast<const float4*>(x) + (size_t)b * Cv * N4v;
    float4 a0 = {0, 0, 0, 0}, a1 = a0, a2 = a0, a3 = a0;
    int p0 = cc * PCH;
#pragma unroll 4
    for (int pp = 0; pp < PCH; ++pp) {
        int p = p0 + pp;
        float4 w  = g_wsc[b][p];
        float4 xv = xb[(size_t)p * N4v + t];
        a0.x = fmaf(w.x, xv.x, a0.x); a0.y = fmaf(w.x, xv.y, a0.y);
        a0.z = fmaf(w.x, xv.z, a0.z); a0.w = fmaf(w.x, xv.w, a0.w);
        a1.x = fmaf(w.y, xv.x, a1.x); a1.y = fmaf(w.y, xv.y, a1.y);
        a1.z = fmaf(w.y, xv.z, a1.z); a1.w = fmaf(w.y, xv.w, a1.w);
        a2.x = fmaf(w.z, xv.x, a2.x); a2.y = fmaf(w.z, xv.y, a2.y);
        a2.z = fmaf(w.z, xv.z, a2.z); a2.w = fmaf(w.z, xv.w, a2.w);
        a3.x = fmaf(w.w, xv.x, a3.x); a3.y = fmaf(w.w, xv.y, a3.y);
        a3.z = fmaf(w.w, xv.z, a3.z); a3.w = fmaf(w.w, xv.w, a3.w);
    }
    g_tpart[b][cc][0][t] = a0;
    g_tpart[b][cc][1][t] = a1;
    g_tpart[b][cc][2][t] = a2;
    g_tpart[b][cc][3][t] = a3;
}

// ---------------------------------------------------------------------------
// Kernel C: reduce p-chunk partials, sigmoid, per-model sum of squares,
// h[b,n] = sum_m g/s. Grid 32, 800 threads (25 full warps; n>=784 inert).
// ---------------------------------------------------------------------------
__global__ void __launch_bounds__(800) kC() {
    int b = blockIdx.x;
    int n = threadIdx.x;
    float g0 = 0.f, g1 = 0.f, g2 = 0.f, g3 = 0.f;
    if (n < Nv) {
        const float* tp = reinterpret_cast<const float*>(&g_tpart[b][0][0][0]);
        float t0 = 0.f, t1 = 0.f, t2 = 0.f, t3 = 0.f;
#pragma unroll
        for (int c = 0; c < NCH; ++c) {
            t0 += tp[(c * Mv + 0) * Nv + n];
            t1 += tp[(c * Mv + 1) * Nv + n];
            t2 += tp[(c * Mv + 2) * Nv + n];
            t3 += tp[(c * Mv + 3) * Nv + n];
        }
        g0 = 1.f / (1.f + __expf(-t0));
        g1 = 1.f / (1.f + __expf(-t1));
        g2 = 1.f / (1.f + __expf(-t2));
        g3 = 1.f / (1.f + __expf(-t3));
    }
    float s0 = g0 * g0, s1 = g1 * g1, s2 = g2 * g2, s3 = g3 * g3;
#pragma unroll
    for (int o = 16; o; o >>= 1) {
        s0 += __shfl_xor_sync(0xffffffffu, s0, o);
        s1 += __shfl_xor_sync(0xffffffffu, s1, o);
        s2 += __shfl_xor_sync(0xffffffffu, s2, o);
        s3 += __shfl_xor_sync(0xffffffffu, s3, o);
    }
    __shared__ float sm[4];
    if (threadIdx.x < 4) sm[threadIdx.x] = 0.f;
    __syncthreads();
    if ((threadIdx.x & 31) == 0) {
        atomicAdd(&sm[0], s0);
        atomicAdd(&sm[1], s1);
        atomicAdd(&sm[2], s2);
        atomicAdd(&sm[3], s3);
    }
    __syncthreads();
    if (n < Nv) {
        float h = g0 / sm[0] + g1 / sm[1] + g2 / sm[2] + g3 / sm[3];
        reinterpret_cast<float*>(&g_h[b][0])[n] = h;
    }
}

// ---------------------------------------------------------------------------
// Kernel D: out[b,p] = invnorm[b,p] * dot(x[b,p,:], h[b,:]).
// Grid (32, 128), 256 threads; warp per p; h staged in SMEM per block.
// ---------------------------------------------------------------------------
__global__ void __launch_bounds__(256) kD(const float* __restrict__ x,
                                          float* __restrict__ out) {
    int b = blockIdx.x;
    int warp = threadIdx.x >> 5, lane = threadIdx.x & 31;
    int p = (blockIdx.y << 3) + warp;
    __shared__ float4 sh[N4v];
    for (int k = threadIdx.x; k < N4v; k += 256) sh[k] = g_h[b][k];
    __syncthreads();
    const float4* row = reinterpret_cast<const float4*>(x) + ((size_t)b * Cv + p) * N4v;
    float s = 0.f;
#pragma unroll
    for (int k = 0; k < 7; ++k) {
        int idx = lane + k * 32;
        if (idx < N4v) {
            float4 v = row[idx];
            float4 h = sh[idx];
            s += v.x * h.x + v.y * h.y + v.z * h.z + v.w * h.w;
        }
    }
#pragma unroll
    for (int o = 16; o; o >>= 1) s += __shfl_xor_sync(0xffffffffu, s, o);
    if (lane == 0) out[b * Cv + p] = s * g_invnorm[b][p];
}

extern "C" void kernel_launch(void* const* d_in, const int* in_sizes, int n_in,
                              void* d_out, int out_size) {
    const float* x  = (const float*)d_in[0];   // [32,1024,28,28] f32
    const float* Wm = (const float*)d_in[1];   // [4,1,1024] f32
    float* out = (float*)d_out;                // [32,1024] f32

    kA<<<dim3(32, 128), 256>>>(x, Wm);
    kB<<<dim3(32, 8), 196>>>(x);
    kC<<<32, 800>>>();
    kD<<<dim3(32, 128), 256>>>(x, out);
}

// round 2
// speedup vs baseline: 1.5214x; 1.5214x over previous
#include <cuda_runtime.h>

// Problem dims
#define Bv 32
#define Cv 1024
#define Nv 784
#define Mv 4
#define N4v 196      // Nv/4
#define ROWS 16      // p-rows per block in fused kernel
#define NCH 64       // Cv/ROWS chunks

// Scratch (device globals — no allocation allowed)
__device__ float  g_invnorm[Bv][Cv];
__device__ float4 g_tpart[Bv][NCH][Mv][N4v];     // partial t over p-chunks
__device__ float4 g_h[Bv][N4v];                  // h[b,n] = sum_m g/s

extern __shared__ float4 smem_dyn[];

// ---------------------------------------------------------------------------
// Fused kernel AB: one block = (b, chunk of 16 p-rows).
// Phase 1: stage the contiguous 50 KB chunk of x into smem (single DRAM read).
// Phase 2: per-row L2 norm from smem; build wsc[m] = Wm[m,p]*invnorm.
// Phase 3: t-partials: thread t owns pixel-quad, loops 16 rows from smem.
// ---------------------------------------------------------------------------
__global__ void __launch_bounds__(256) kAB(const float* __restrict__ x,
                                           const float* __restrict__ Wm) {
    float4* sx   = smem_dyn;             // [ROWS*N4v]
    float4* swsc = smem_dyn + ROWS * N4v; // [ROWS]
    int b = blockIdx.x, ch = blockIdx.y;
    int p0 = ch * ROWS;
    const float4* src = reinterpret_cast<const float4*>(x) + ((size_t)b * Cv + p0) * N4v;

    // Phase 1: contiguous cooperative load (3136 float4)
#pragma unroll
    for (int i = threadIdx.x; i < ROWS * N4v; i += 256) sx[i] = src[i];
    __syncthreads();

    // Phase 2: norms (8 warps x 2 rows)
    int warp = threadIdx.x >> 5, lane = threadIdx.x & 31;
#pragma unroll
    for (int r = warp; r < ROWS; r += 8) {
        float s = 0.f;
#pragma unroll
        for (int k = 0; k < 7; ++k) {
            int idx = lane + k * 32;
            if (idx < N4v) {
                float4 v = sx[r * N4v + idx];
                s += v.x * v.x + v.y * v.y + v.z * v.z + v.w * v.w;
            }
        }
#pragma unroll
        for (int o = 16; o; o >>= 1) s += __shfl_xor_sync(0xffffffffu, s, o);
        if (lane == 0) {
            float inv = 1.0f / fmaxf(sqrtf(s), 1e-10f);
            int p = p0 + r;
            g_invnorm[b][p] = inv;
            float4 w;
            w.x = Wm[0 * Cv + p] * inv;
            w.y = Wm[1 * Cv + p] * inv;
            w.z = Wm[2 * Cv + p] * inv;
            w.w = Wm[3 * Cv + p] * inv;
            swsc[r] = w;
        }
    }
    __syncthreads();

    // Phase 3: accumulate t partials over the 16 rows
    int t = threadIdx.x;
    if (t < N4v) {
        float4 a0 = {0, 0, 0, 0}, a1 = a0, a2 = a0, a3 = a0;
#pragma unroll
        for (int r = 0; r < ROWS; ++r) {
            float4 w  = swsc[r];
            float4 xv = sx[r * N4v + t];
            a0.x = fmaf(w.x, xv.x, a0.x); a0.y = fmaf(w.x, xv.y, a0.y);
            a0.z = fmaf(w.x, xv.z, a0.z); a0.w = fmaf(w.x, xv.w, a0.w);
            a1.x = fmaf(w.y, xv.x, a1.x); a1.y = fmaf(w.y, xv.y, a1.y);
            a1.z = fmaf(w.y, xv.z, a1.z); a1.w = fmaf(w.y, xv.w, a1.w);
            a2.x = fmaf(w.z, xv.x, a2.x); a2.y = fmaf(w.z, xv.y, a2.y);
            a2.z = fmaf(w.z, xv.z, a2.z); a2.w = fmaf(w.z, xv.w, a2.w);
            a3.x = fmaf(w.w, xv.x, a3.x); a3.y = fmaf(w.w, xv.y, a3.y);
            a3.z = fmaf(w.w, xv.z, a3.z); a3.w = fmaf(w.w, xv.w, a3.w);
        }
        g_tpart[b][ch][0][t] = a0;
        g_tpart[b][ch][1][t] = a1;
        g_tpart[b][ch][2][t] = a2;
        g_tpart[b][ch][3][t] = a3;
    }
}

// ---------------------------------------------------------------------------
// Kernel C: reduce 64 p-chunk partials, sigmoid, per-model sum of squares,
// h[b,n] = sum_m g/s. Grid 32, 800 threads (25 warps; n>=784 inert).
// ---------------------------------------------------------------------------
__global__ void __launch_bounds__(800) kC() {
    int b = blockIdx.x;
    int n = threadIdx.x;
    float g0 = 0.f, g1 = 0.f, g2 = 0.f, g3 = 0.f;
    if (n < Nv) {
        const float* tp = reinterpret_cast<const float*>(&g_tpart[b][0][0][0]);
        float t0 = 0.f, t1 = 0.f, t2 = 0.f, t3 = 0.f;
#pragma unroll 8
        for (int c = 0; c < NCH; ++c) {
            t0 += tp[(c * Mv + 0) * Nv + n];
            t1 += tp[(c * Mv + 1) * Nv + n];
            t2 += tp[(c * Mv + 2) * Nv + n];
            t3 += tp[(c * Mv + 3) * Nv + n];
        }
        g0 = 1.f / (1.f + __expf(-t0));
        g1 = 1.f / (1.f + __expf(-t1));
        g2 = 1.f / (1.f + __expf(-t2));
        g3 = 1.f / (1.f + __expf(-t3));
    }
    float s0 = g0 * g0, s1 = g1 * g1, s2 = g2 * g2, s3 = g3 * g3;
#pragma unroll
    for (int o = 16; o; o >>= 1) {
        s0 += __shfl_xor_sync(0xffffffffu, s0, o);
        s1 += __shfl_xor_sync(0xffffffffu, s1, o);
        s2 += __shfl_xor_sync(0xffffffffu, s2, o);
        s3 += __shfl_xor_sync(0xffffffffu, s3, o);
    }
    __shared__ float sm[4];
    if (threadIdx.x < 4) sm[threadIdx.x] = 0.f;
    __syncthreads();
    if ((threadIdx.x & 31) == 0) {
        atomicAdd(&sm[0], s0);
        atomicAdd(&sm[1], s1);
        atomicAdd(&sm[2], s2);
        atomicAdd(&sm[3], s3);
    }
    __syncthreads();
    if (n < Nv) {
        float h = g0 / sm[0] + g1 / sm[1] + g2 / sm[2] + g3 / sm[3];
        reinterpret_cast<float*>(&g_h[b][0])[n] = h;
    }
}

// ---------------------------------------------------------------------------
// Kernel D: out[b,p] = invnorm[b,p] * dot(x[b,p,:], h[b,:]).
// Grid (32, 128), 256 threads; warp per p; h staged in SMEM per block.
// ---------------------------------------------------------------------------
__global__ void __launch_bounds__(256) kD(const float* __restrict__ x,
                                          float* __restrict__ out) {
    int b = blockIdx.x;
    int warp = threadIdx.x >> 5, lane = threadIdx.x & 31;
    int p = (blockIdx.y << 3) + warp;
    __shared__ float4 sh[N4v];
    for (int k = threadIdx.x; k < N4v; k += 256) sh[k] = g_h[b][k];
    __syncthreads();
    const float4* row = reinterpret_cast<const float4*>(x) + ((size_t)b * Cv + p) * N4v;
    float s = 0.f;
#pragma unroll
    for (int k = 0; k < 7; ++k) {
        int idx = lane + k * 32;
        if (idx < N4v) {
            float4 v = row[idx];
            float4 h = sh[idx];
            s += v.x * h.x + v.y * h.y + v.z * h.z + v.w * h.w;
        }
    }
#pragma unroll
    for (int o = 16; o; o >>= 1) s += __shfl_xor_sync(0xffffffffu, s, o);
    if (lane == 0) out[b * Cv + p] = s * g_invnorm[b][p];
}

extern "C" void kernel_launch(void* const* d_in, const int* in_sizes, int n_in,
                              void* d_out, int out_size) {
    const float* x  = (const float*)d_in[0];   // [32,1024,28,28] f32
    const float* Wm = (const float*)d_in[1];   // [4,1,1024] f32
    float* out = (float*)d_out;                // [32,1024] f32

    static const int smem_bytes = (ROWS * N4v + ROWS) * sizeof(float4);  // 50432
    cudaFuncSetAttribute(kAB, cudaFuncAttributeMaxDynamicSharedMemorySize, smem_bytes);

    kAB<<<dim3(32, 64), 256, smem_bytes>>>(x, Wm);
    kC<<<32, 800>>>();
    kD<<<dim3(32, 128), 256>>>(x, out);
}

// round 3
// speedup vs baseline: 1.7441x; 1.1463x over previous
#include <cuda_runtime.h>
#include <cstdint>

// Problem dims
#define Bv 32
#define Cv 1024
#define Nv 784
#define Mv 4
#define N4v 196      // Nv/4
#define GROWS 8      // rows per generation
#define GEN 4        // generations per block
#define BROWS 32     // GROWS*GEN rows per block
#define NCH 32       // Cv/BROWS chunks

// Scratch (device globals — no allocation allowed)
__device__ float  g_invnorm[Bv][Cv];
__device__ float4 g_tpart[Bv][NCH][Mv][N4v];   // partial t over p-chunks (12.8 MB)
__device__ float4 g_g[Bv][Mv][N4v];            // sigmoid activations
__device__ float  g_spart[Bv][2][Mv];          // partial sum of g^2 per n-half

__device__ __forceinline__ void cp_async16(uint32_t saddr, const void* gaddr) {
    asm volatile("cp.async.cg.shared.global [%0], [%1], 16;\n" :: "r"(saddr), "l"(gaddr));
}
__device__ __forceinline__ void cp_commit() {
    asm volatile("cp.async.commit_group;\n");
}
template <int N>
__device__ __forceinline__ void cp_wait() {
    asm volatile("cp.async.wait_group %0;\n" :: "n"(N));
}

extern __shared__ float4 smem_dyn[];  // 2 * GROWS*N4v float4 = 50176 B

// ---------------------------------------------------------------------------
// kAB: one block = (b, 32-row chunk). 4 generations of 8 rows, double-buffered
// cp.async pipeline: prefetch gen g+1 while computing norms + t-accumulation
// on gen g. Accumulators live in registers across generations.
// ---------------------------------------------------------------------------
__global__ void __launch_bounds__(256) kAB(const float* __restrict__ x,
                                           const float* __restrict__ Wm) {
    __shared__ float4 swsc[GROWS];
    int b = blockIdx.x, ch = blockIdx.y;
    int p0 = ch * BROWS;
    const float4* base = reinterpret_cast<const float4*>(x) + ((size_t)b * Cv + p0) * N4v;
    int t = threadIdx.x;
    int warp = t >> 5, lane = t & 31;
    uint32_t sbase = (uint32_t)__cvta_generic_to_shared(smem_dyn);

    // prefetch generation 0 into buffer 0
#pragma unroll
    for (int k = 0; k < 7; ++k) {
        int i = t + k * 256;
        if (i < GROWS * N4v) cp_async16(sbase + i * 16u, base + i);
    }
    cp_commit();

    float4 a0 = {0, 0, 0, 0}, a1 = a0, a2 = a0, a3 = a0;

#pragma unroll
    for (int g = 0; g < GEN; ++g) {
        // issue prefetch of next generation into the other buffer
        if (g + 1 < GEN) {
            uint32_t sb = sbase + ((g + 1) & 1) * (GROWS * N4v * 16u);
            const float4* gb = base + (g + 1) * GROWS * N4v;
#pragma unroll
            for (int k = 0; k < 7; ++k) {
                int i = t + k * 256;
                if (i < GROWS * N4v) cp_async16(sb + i * 16u, gb + i);
            }
            cp_commit();
            cp_wait<1>();   // current generation's data is ready
        } else {
            cp_wait<0>();
        }
        __syncthreads();

        float4* cur = smem_dyn + (g & 1) * (GROWS * N4v);

        // norms: warp w handles row w (8 warps, 8 rows)
        {
            float s = 0.f;
#pragma unroll
            for (int k = 0; k < 7; ++k) {
                int idx = lane + k * 32;
                if (idx < N4v) {
                    float4 v = cur[warp * N4v + idx];
                    s += v.x * v.x + v.y * v.y + v.z * v.z + v.w * v.w;
                }
            }
#pragma unroll
            for (int o = 16; o; o >>= 1) s += __shfl_xor_sync(0xffffffffu, s, o);
            if (lane == 0) {
                float inv = 1.0f / fmaxf(sqrtf(s), 1e-10f);
                int p = p0 + g * GROWS + warp;
                g_invnorm[b][p] = inv;
                float4 w;
                w.x = Wm[0 * Cv + p] * inv;
                w.y = Wm[1 * Cv + p] * inv;
                w.z = Wm[2 * Cv + p] * inv;
                w.w = Wm[3 * Cv + p] * inv;
                swsc[warp] = w;
            }
        }
        __syncthreads();

        // t-accumulation for this generation's 8 rows
        if (t < N4v) {
#pragma unroll
            for (int r = 0; r < GROWS; ++r) {
                float4 w  = swsc[r];
                float4 xv = cur[r * N4v + t];
                a0.x = fmaf(w.x, xv.x, a0.x); a0.y = fmaf(w.x, xv.y, a0.y);
                a0.z = fmaf(w.x, xv.z, a0.z); a0.w = fmaf(w.x, xv.w, a0.w);
                a1.x = fmaf(w.y, xv.x, a1.x); a1.y = fmaf(w.y, xv.y, a1.y);
                a1.z = fmaf(w.y, xv.z, a1.z); a1.w = fmaf(w.y, xv.w, a1.w);
                a2.x = fmaf(w.z, xv.x, a2.x); a2.y = fmaf(w.z, xv.y, a2.y);
                a2.z = fmaf(w.z, xv.z, a2.z); a2.w = fmaf(w.z, xv.w, a2.w);
                a3.x = fmaf(w.w, xv.x, a3.x); a3.y = fmaf(w.w, xv.y, a3.y);
                a3.z = fmaf(w.w, xv.z, a3.z); a3.w = fmaf(w.w, xv.w, a3.w);
            }
        }
        __syncthreads();  // protect swsc + buffer before next gen's writes
    }

    if (t < N4v) {
        g_tpart[b][ch][0][t] = a0;
        g_tpart[b][ch][1][t] = a1;
        g_tpart[b][ch][2][t] = a2;
        g_tpart[b][ch][3][t] = a3;
    }
}

// ---------------------------------------------------------------------------
// kC1: grid (32, 2), 128 threads. Each thread owns one pixel-quad in its
// n-half: reduce 32 chunk partials per model, sigmoid, store g, and write
// per-half partial sums of g^2.
// ---------------------------------------------------------------------------
__global__ void __launch_bounds__(128) kC1() {
    int b = blockIdx.x, half = blockIdx.y;
    int t = threadIdx.x;
    int q = half * 98 + t;
    bool valid = (t < 98);
    float4 t0 = {0,0,0,0}, t1 = t0, t2 = t0, t3 = t0;
    if (valid) {
#pragma unroll 8
        for (int c = 0; c < NCH; ++c) {
            float4 v0 = g_tpart[b][c][0][q];
            float4 v1 = g_tpart[b][c][1][q];
            float4 v2 = g_tpart[b][c][2][q];
            float4 v3 = g_tpart[b][c][3][q];
            t0.x += v0.x; t0.y += v0.y; t0.z += v0.z; t0.w += v0.w;
            t1.x += v1.x; t1.y += v1.y; t1.z += v1.z; t1.w += v1.w;
            t2.x += v2.x; t2.y += v2.y; t2.z += v2.z; t2.w += v2.w;
            t3.x += v3.x; t3.y += v3.y; t3.z += v3.z; t3.w += v3.w;
        }
    }
    auto sig4 = [](float4 v) {
        float4 r;
        r.x = 1.f / (1.f + __expf(-v.x));
        r.y = 1.f / (1.f + __expf(-v.y));
        r.z = 1.f / (1.f + __expf(-v.z));
        r.w = 1.f / (1.f + __expf(-v.w));
        return r;
    };
    float4 gg0 = sig4(t0), gg1 = sig4(t1), gg2 = sig4(t2), gg3 = sig4(t3);
    float s0 = 0, s1 = 0, s2 = 0, s3 = 0;
    if (valid) {
        g_g[b][0][q] = gg0; g_g[b][1][q] = gg1;
        g_g[b][2][q] = gg2; g_g[b][3][q] = gg3;
        s0 = gg0.x*gg0.x + gg0.y*gg0.y + gg0.z*gg0.z + gg0.w*gg0.w;
        s1 = gg1.x*gg1.x + gg1.y*gg1.y + gg1.z*gg1.z + gg1.w*gg1.w;
        s2 = gg2.x*gg2.x + gg2.y*gg2.y + gg2.z*gg2.z + gg2.w*gg2.w;
        s3 = gg3.x*gg3.x + gg3.y*gg3.y + gg3.z*gg3.z + gg3.w*gg3.w;
    }
#pragma unroll
    for (int o = 16; o; o >>= 1) {
        s0 += __shfl_xor_sync(0xffffffffu, s0, o);
        s1 += __shfl_xor_sync(0xffffffffu, s1, o);
        s2 += __shfl_xor_sync(0xffffffffu, s2, o);
        s3 += __shfl_xor_sync(0xffffffffu, s3, o);
    }
    __shared__ float sm[4];
    if (t < 4) sm[t] = 0.f;
    __syncthreads();
    if ((t & 31) == 0) {
        atomicAdd(&sm[0], s0);
        atomicAdd(&sm[1], s1);
        atomicAdd(&sm[2], s2);
        atomicAdd(&sm[3], s3);
    }
    __syncthreads();
    if (t < 4) g_spart[b][half][t] = sm[t];
}

// ---------------------------------------------------------------------------
// kD: prologue builds h[b,n] = sum_m g/s in smem from g_g + g_spart (L2-hot),
// then out[b,p] = invnorm[b,p] * dot(x[b,p,:], h[b,:]). Warp per p.
// ---------------------------------------------------------------------------
__global__ void __launch_bounds__(256) kD(const float* __restrict__ x,
                                          float* __restrict__ out) {
    int b = blockIdx.x;
    int warp = threadIdx.x >> 5, lane = threadIdx.x & 31;
    int p = (blockIdx.y << 3) + warp;
    __shared__ float4 sh[N4v];
    __shared__ float ss[4];
    if (threadIdx.x < 4)
        ss[threadIdx.x] = 1.f / (g_spart[b][0][threadIdx.x] + g_spart[b][1][threadIdx.x]);
    __syncthreads();
    if (threadIdx.x < N4v) {
        int q = threadIdx.x;
        float i0 = ss[0], i1 = ss[1], i2 = ss[2], i3 = ss[3];
        float4 gg0 = g_g[b][0][q], gg1 = g_g[b][1][q];
        float4 gg2 = g_g[b][2][q], gg3 = g_g[b][3][q];
        float4 h;
        h.x = gg0.x*i0 + gg1.x*i1 + gg2.x*i2 + gg3.x*i3;
        h.y = gg0.y*i0 + gg1.y*i1 + gg2.y*i2 + gg3.y*i3;
        h.z = gg0.z*i0 + gg1.z*i1 + gg2.z*i2 + gg3.z*i3;
        h.w = gg0.w*i0 + gg1.w*i1 + gg2.w*i2 + gg3.w*i3;
        sh[q] = h;
    }
    __syncthreads();
    const float4* row = reinterpret_cast<const float4*>(x) + ((size_t)b * Cv + p) * N4v;
    float s = 0.f;
#pragma unroll
    for (int k = 0; k < 7; ++k) {
        int idx = lane + k * 32;
        if (idx < N4v) {
            float4 v = row[idx];
            float4 h = sh[idx];
            s += v.x * h.x + v.y * h.y + v.z * h.z + v.w * h.w;
        }
    }
#pragma unroll
    for (int o = 16; o; o >>= 1) s += __shfl_xor_sync(0xffffffffu, s, o);
    if (lane == 0) out[b * Cv + p] = s * g_invnorm[b][p];
}

extern "C" void kernel_launch(void* const* d_in, const int* in_sizes, int n_in,
                              void* d_out, int out_size) {
    const float* x  = (const float*)d_in[0];   // [32,1024,28,28] f32
    const float* Wm = (const float*)d_in[1];   // [4,1,1024] f32
    float* out = (float*)d_out;                // [32,1024] f32

    static const int smem_bytes = 2 * GROWS * N4v * sizeof(float4);  // 50176
    cudaFuncSetAttribute(kAB, cudaFuncAttributeMaxDynamicSharedMemorySize, smem_bytes);

    kAB<<<dim3(32, NCH), 256, smem_bytes>>>(x, Wm);
    kC1<<<dim3(32, 2), 128>>>();
    kD<<<dim3(32, 128), 256>>>(x, out);
}

// round 4
// speedup vs baseline: 1.9080x; 1.0940x over previous
#include <cuda_runtime.h>
#include <cstdint>

// Problem dims
#define Bv 32
#define Cv 1024
#define Nv 784
#define Mv 4
#define N4v 196      // Nv/4
#define BROWS 32     // rows per kAB block
#define CHUNKS 32    // Cv/BROWS

// Scratch (device globals — zero-initialized at load; kC restores zeros)
__device__ float  g_invnorm[Bv][Cv];
__device__ float4 g_t[Bv][Mv][N4v];   // RED-accumulated t (400 KB)
__device__ float4 g_h[Bv][N4v];       // h[b,n] = sum_m g/s

// ---------------------------------------------------------------------------
// kAB: block = (b, 32-row chunk). Phase 1: warp-per-row L2 norms straight from
// DRAM (bytes land in L2). Phase 2: thread-per-quad accumulation re-reading
// the same 100 KB via L2 hits; RED-flush partials into g_t.
// ---------------------------------------------------------------------------
__global__ void __launch_bounds__(256) kAB(const float* __restrict__ x,
                                           const float* __restrict__ Wm) {
    __shared__ float4 swsc[BROWS];
    int b = blockIdx.x, ch = blockIdx.y;
    int p0 = ch * BROWS;
    int t = threadIdx.x;
    int warp = t >> 5, lane = t & 31;
    const float4* base = reinterpret_cast<const float4*>(x) + ((size_t)b * Cv + p0) * N4v;

    // Phase 1: each warp norms 4 rows (8 warps x 4 = 32 rows)
#pragma unroll
    for (int rr = 0; rr < 4; ++rr) {
        int r = warp + rr * 8;
        const float4* row = base + (size_t)r * N4v;
        float s = 0.f;
#pragma unroll
        for (int k = 0; k < 7; ++k) {
            int idx = lane + k * 32;
            if (idx < N4v) {
                float4 v = row[idx];
                s += v.x * v.x + v.y * v.y + v.z * v.z + v.w * v.w;
            }
        }
#pragma unroll
        for (int o = 16; o; o >>= 1) s += __shfl_xor_sync(0xffffffffu, s, o);
        if (lane == 0) {
            float inv = 1.0f / fmaxf(sqrtf(s), 1e-10f);
            int p = p0 + r;
            g_invnorm[b][p] = inv;
            float4 w;
            w.x = Wm[0 * Cv + p] * inv;
            w.y = Wm[1 * Cv + p] * inv;
            w.z = Wm[2 * Cv + p] * inv;
            w.w = Wm[3 * Cv + p] * inv;
            swsc[r] = w;
        }
    }
    __syncthreads();

    // Phase 2: thread-per-quad, loop 32 rows (L2-hot re-reads)
    if (t < N4v) {
        float4 a0 = {0, 0, 0, 0}, a1 = a0, a2 = a0, a3 = a0;
#pragma unroll 4
        for (int r = 0; r < BROWS; ++r) {
            float4 w  = swsc[r];
            float4 xv = base[(size_t)r * N4v + t];
            a0.x = fmaf(w.x, xv.x, a0.x); a0.y = fmaf(w.x, xv.y, a0.y);
            a0.z = fmaf(w.x, xv.z, a0.z); a0.w = fmaf(w.x, xv.w, a0.w);
            a1.x = fmaf(w.y, xv.x, a1.x); a1.y = fmaf(w.y, xv.y, a1.y);
            a1.z = fmaf(w.y, xv.z, a1.z); a1.w = fmaf(w.y, xv.w, a1.w);
            a2.x = fmaf(w.z, xv.x, a2.x); a2.y = fmaf(w.z, xv.y, a2.y);
            a2.z = fmaf(w.z, xv.z, a2.z); a2.w = fmaf(w.z, xv.w, a2.w);
            a3.x = fmaf(w.w, xv.x, a3.x); a3.y = fmaf(w.w, xv.y, a3.y);
            a3.z = fmaf(w.w, xv.z, a3.z); a3.w = fmaf(w.w, xv.w, a3.w);
        }
        float* d0 = reinterpret_cast<float*>(&g_t[b][0][t]);
        float* d1 = reinterpret_cast<float*>(&g_t[b][1][t]);
        float* d2 = reinterpret_cast<float*>(&g_t[b][2][t]);
        float* d3 = reinterpret_cast<float*>(&g_t[b][3][t]);
        atomicAdd(d0 + 0, a0.x); atomicAdd(d0 + 1, a0.y);
        atomicAdd(d0 + 2, a0.z); atomicAdd(d0 + 3, a0.w);
        atomicAdd(d1 + 0, a1.x); atomicAdd(d1 + 1, a1.y);
        atomicAdd(d1 + 2, a1.z); atomicAdd(d1 + 3, a1.w);
        atomicAdd(d2 + 0, a2.x); atomicAdd(d2 + 1, a2.y);
        atomicAdd(d2 + 2, a2.z); atomicAdd(d2 + 3, a2.w);
        atomicAdd(d3 + 0, a3.x); atomicAdd(d3 + 1, a3.y);
        atomicAdd(d3 + 2, a3.z); atomicAdd(d3 + 3, a3.w);
    }
}

// ---------------------------------------------------------------------------
// kC: grid 32 (one block per b), 224 threads (7 full warps, 196 active).
// Sigmoid, per-model sum of g^2, h = sum_m g/s; then RE-ZERO g_t for the
// next call (device globals start zero, so every call sees zeros).
// ---------------------------------------------------------------------------
__global__ void __launch_bounds__(224) kC() {
    int b = blockIdx.x;
    int t = threadIdx.x;
    bool valid = (t < N4v);
    float4 gg0 = {0,0,0,0}, gg1 = gg0, gg2 = gg0, gg3 = gg0;
    if (valid) {
        float4 t0 = g_t[b][0][t], t1 = g_t[b][1][t];
        float4 t2 = g_t[b][2][t], t3 = g_t[b][3][t];
        auto sig4 = [](float4 v) {
            float4 r;
            r.x = 1.f / (1.f + __expf(-v.x));
            r.y = 1.f / (1.f + __expf(-v.y));
            r.z = 1.f / (1.f + __expf(-v.z));
            r.w = 1.f / (1.f + __expf(-v.w));
            return r;
        };
        gg0 = sig4(t0); gg1 = sig4(t1); gg2 = sig4(t2); gg3 = sig4(t3);
    }
    float s0 = gg0.x*gg0.x + gg0.y*gg0.y + gg0.z*gg0.z + gg0.w*gg0.w;
    float s1 = gg1.x*gg1.x + gg1.y*gg1.y + gg1.z*gg1.z + gg1.w*gg1.w;
    float s2 = gg2.x*gg2.x + gg2.y*gg2.y + gg2.z*gg2.z + gg2.w*gg2.w;
    float s3 = gg3.x*gg3.x + gg3.y*gg3.y + gg3.z*gg3.z + gg3.w*gg3.w;
#pragma unroll
    for (int o = 16; o; o >>= 1) {
        s0 += __shfl_xor_sync(0xffffffffu, s0, o);
        s1 += __shfl_xor_sync(0xffffffffu, s1, o);
        s2 += __shfl_xor_sync(0xffffffffu, s2, o);
        s3 += __shfl_xor_sync(0xffffffffu, s3, o);
    }
    __shared__ float sm[4];
    if (t < 4) sm[t] = 0.f;
    __syncthreads();
    if ((t & 31) == 0) {
        atomicAdd(&sm[0], s0);
        atomicAdd(&sm[1], s1);
        atomicAdd(&sm[2], s2);
        atomicAdd(&sm[3], s3);
    }
    __syncthreads();
    if (valid) {
        float i0 = 1.f / sm[0], i1 = 1.f / sm[1], i2 = 1.f / sm[2], i3 = 1.f / sm[3];
        float4 h;
        h.x = gg0.x*i0 + gg1.x*i1 + gg2.x*i2 + gg3.x*i3;
        h.y = gg0.y*i0 + gg1.y*i1 + gg2.y*i2 + gg3.y*i3;
        h.z = gg0.z*i0 + gg1.z*i1 + gg2.z*i2 + gg3.z*i3;
        h.w = gg0.w*i0 + gg1.w*i1 + gg2.w*i2 + gg3.w*i3;
        g_h[b][t] = h;
        // restore zeros for the next call's RED accumulation
        float4 z = {0, 0, 0, 0};
        g_t[b][0][t] = z; g_t[b][1][t] = z;
        g_t[b][2][t] = z; g_t[b][3][t] = z;
    }
}

// ---------------------------------------------------------------------------
// kD: out[b,p] = invnorm[b,p] * dot(x[b,p,:], h[b,:]). Warp per p; h in smem.
// ---------------------------------------------------------------------------
__global__ void __launch_bounds__(256) kD(const float* __restrict__ x,
                                          float* __restrict__ out) {
    int b = blockIdx.x;
    int warp = threadIdx.x >> 5, lane = threadIdx.x & 31;
    int p = (blockIdx.y << 3) + warp;
    __shared__ float4 sh[N4v];
    if (threadIdx.x < N4v) sh[threadIdx.x] = g_h[b][threadIdx.x];
    __syncthreads();
    const float4* row = reinterpret_cast<const float4*>(x) + ((size_t)b * Cv + p) * N4v;
    float s = 0.f;
#pragma unroll
    for (int k = 0; k < 7; ++k) {
        int idx = lane + k * 32;
        if (idx < N4v) {
            float4 v = row[idx];
            float4 h = sh[idx];
            s += v.x * h.x + v.y * h.y + v.z * h.z + v.w * h.w;
        }
    }
#pragma unroll
    for (int o = 16; o; o >>= 1) s += __shfl_xor_sync(0xffffffffu, s, o);
    if (lane == 0) out[b * Cv + p] = s * g_invnorm[b][p];
}

extern "C" void kernel_launch(void* const* d_in, const int* in_sizes, int n_in,
                              void* d_out, int out_size) {
    const float* x  = (const float*)d_in[0];   // [32,1024,28,28] f32
    const float* Wm = (const float*)d_in[1];   // [4,1,1024] f32
    float* out = (float*)d_out;                // [32,1024] f32

    kAB<<<dim3(32, CHUNKS), 256>>>(x, Wm);
    kC<<<32, 224>>>();
    kD<<<dim3(32, 128), 256>>>(x, out);
}